// round 5
// baseline (speedup 1.0000x reference)
#include <cuda_runtime.h>
#include <cuda_bf16.h>
#include <cstdint>

// channel-interleaved logits on the 14^3 grid, pre-scaled by log2(e):
// g_z4[v*4 + c]  (43 KB)
__device__ float g_z4[2744 * 4];

#define LOG2E 1.4426950408889634f
#define SCALE (13.0f / 223.0f)

// ---------------------------------------------------------------------------
// Kernel 1: 1x1x1 conv on the small grid -> interleaved float4 logits.
// ---------------------------------------------------------------------------
__global__ void conv_small_kernel(const float* __restrict__ x,
                                  const float* __restrict__ W,
                                  const float* __restrict__ b) {
    int idx = blockIdx.x * blockDim.x + threadIdx.x;
    if (idx >= 4 * 2744) return;
    int v = idx >> 2;
    int o = idx & 3;
    float acc = b[o];
    const float* wrow = W + o * 32;
#pragma unroll
    for (int c = 0; c < 32; c++) {
        acc = fmaf(wrow[c], x[c * 2744 + v], acc);
    }
    g_z4[idx] = acc * LOG2E;   // coalesced interleaved write
}

// ---------------------------------------------------------------------------
// Kernel 2: block (14,16) = one d, 16 consecutive h rows. Each thread:
//  Fill: bilinear (d,h)-lerp of the 4-channel value at iw=tx into smem
//        (4x LDG.128 from interleaved logits), dup entry at iw=14.
//  Main: 16 consecutive w voxels. 15 steps span 0.874 < 1 source unit, so at
//        most ONE knot crossing: G0,G1,G2 loaded once, continuous form
//        z = G0 + u*(G1-G0) + v*(G2-G1), u=min(t,1), v=t-u.
//  Softmax via channel-0 diffs: p_i = e^{d_i} / (1 + sum e^{d_j}),
//        3x MUFU.EX2 + 1x MUFU.RCP per voxel. 16x STG.128 per thread.
// ---------------------------------------------------------------------------
__global__ __launch_bounds__(224) void upsample_softmax_kernel(float* __restrict__ out) {
    __shared__ __align__(16) float4 gs[16][16];   // 15 used (14 + dup)

    const int tx = threadIdx.x;   // 0..13
    const int ty = threadIdx.y;   // 0..15
    const int d  = blockIdx.y;
    const int h  = blockIdx.x * 16 + ty;

    // ---- fill gs[ty][tx] ----
    {
        float pd = (float)d * SCALE;
        int id0 = (int)pd; if (id0 > 12) id0 = 12;
        float wd = pd - (float)id0;
        float ph = (float)h * SCALE;
        int ih0 = (int)ph; if (ih0 > 12) ih0 = 12;
        float wh = ph - (float)ih0;

        const float4* z4 = (const float4*)g_z4;
        int base = (id0 * 14 + ih0) * 14 + tx;
        float4 z00 = z4[base];
        float4 z01 = z4[base + 14];
        float4 z10 = z4[base + 196];
        float4 z11 = z4[base + 210];
        float4 a0, a1, g;
        a0.x = fmaf(wh, z01.x - z00.x, z00.x);
        a0.y = fmaf(wh, z01.y - z00.y, z00.y);
        a0.z = fmaf(wh, z01.z - z00.z, z00.z);
        a0.w = fmaf(wh, z01.w - z00.w, z00.w);
        a1.x = fmaf(wh, z11.x - z10.x, z10.x);
        a1.y = fmaf(wh, z11.y - z10.y, z10.y);
        a1.z = fmaf(wh, z11.z - z10.z, z10.z);
        a1.w = fmaf(wh, z11.w - z10.w, z10.w);
        g.x = fmaf(wd, a1.x - a0.x, a0.x);
        g.y = fmaf(wd, a1.y - a0.y, a0.y);
        g.z = fmaf(wd, a1.z - a0.z, a0.z);
        g.w = fmaf(wd, a1.w - a0.w, a0.w);
        gs[ty][tx] = g;
        if (tx == 13) gs[ty][14] = g;   // dup; its segment weight is always ~0
    }
    __syncthreads();

    // ---- 16 consecutive w per thread ----
    const int w0 = tx * 16;
    float pw0 = (float)w0 * SCALE;        // <= 12.13, no clip needed
    int iw0 = (int)pw0;
    float t0 = pw0 - (float)iw0;

    float4 G0 = gs[ty][iw0];
    float4 G1 = gs[ty][iw0 + 1];
    float4 G2 = gs[ty][iw0 + 2];

    // channel-0 diff basis
    float b1 = G0.y - G0.x, b2 = G0.z - G0.x, b3 = G0.w - G0.x;
    float D0 = G1.x - G0.x;
    float P1 = (G1.y - G0.y) - D0;
    float P2 = (G1.z - G0.z) - D0;
    float P3 = (G1.w - G0.w) - D0;
    float E0 = G2.x - G1.x;
    float Q1 = (G2.y - G1.y) - E0;
    float Q2 = (G2.z - G1.z) - E0;
    float Q3 = (G2.w - G1.w) - E0;

    const int PLANE4 = (224 * 224 * 224) >> 2;
    float4* o4 = (float4*)out + (((d * 224 + h) * 224 + w0) >> 2);

    float r0[4], r1[4], r2[4], r3[4];

#pragma unroll
    for (int k = 0; k < 16; k++) {
        float t = t0 + (float)k * SCALE;   // folds to FADD with immediate
        float u = fminf(t, 1.0f);
        float v = t - u;
        float d1 = fmaf(v, Q1, fmaf(u, P1, b1));
        float d2 = fmaf(v, Q2, fmaf(u, P2, b2));
        float d3 = fmaf(v, Q3, fmaf(u, P3, b3));
        float e1 = exp2f(d1);
        float e2 = exp2f(d2);
        float e3 = exp2f(d3);
        float s = 1.0f + e1 + e2 + e3;
        float r;
        asm("rcp.approx.f32 %0, %1;" : "=f"(r) : "f"(s));
        int j = k & 3;
        r0[j] = r;
        r1[j] = e1 * r;
        r2[j] = e2 * r;
        r3[j] = e3 * r;
        if (j == 3) {
            int g = k >> 2;
            o4[g]              = make_float4(r0[0], r0[1], r0[2], r0[3]);
            o4[g + PLANE4]     = make_float4(r1[0], r1[1], r1[2], r1[3]);
            o4[g + 2 * PLANE4] = make_float4(r2[0], r2[1], r2[2], r2[3]);
            o4[g + 3 * PLANE4] = make_float4(r3[0], r3[1], r3[2], r3[3]);
        }
    }
}

extern "C" void kernel_launch(void* const* d_in, const int* in_sizes, int n_in,
                              void* d_out, int out_size) {
    const float* x = (const float*)d_in[0];  // [1,32,14,14,14]
    const float* W = (const float*)d_in[1];  // [4,32]
    const float* b = (const float*)d_in[2];  // [4]
    float* out = (float*)d_out;              // [1,4,224,224,224]

    conv_small_kernel<<<(4 * 2744 + 255) / 256, 256>>>(x, W, b);

    dim3 block(14, 16);
    dim3 grid(14, 224);  // (h-group of 16, d)
    upsample_softmax_kernel<<<grid, block>>>(out);
}

// round 6
// speedup vs baseline: 2.4298x; 2.4298x over previous
#include <cuda_runtime.h>
#include <cuda_bf16.h>
#include <cstdint>

// channel-interleaved logits on the 14^3 grid, pre-scaled by log2(e):
// g_z4[v*4 + c]  (43 KB)
__device__ float g_z4[2744 * 4];

#define LOG2E 1.4426950408889634f
#define SCALE (13.0f / 223.0f)

// ---------------------------------------------------------------------------
// Kernel 1: 1x1x1 conv on the small grid -> interleaved float4 logits.
// ---------------------------------------------------------------------------
__global__ void conv_small_kernel(const float* __restrict__ x,
                                  const float* __restrict__ W,
                                  const float* __restrict__ b) {
    int idx = blockIdx.x * blockDim.x + threadIdx.x;
    if (idx >= 4 * 2744) return;
    int v = idx >> 2;
    int o = idx & 3;
    float acc = b[o];
    const float* wrow = W + o * 32;
#pragma unroll
    for (int c = 0; c < 32; c++) {
        acc = fmaf(wrow[c], x[c * 2744 + v], acc);
    }
    g_z4[idx] = acc * LOG2E;   // coalesced interleaved write
}

// ---------------------------------------------------------------------------
// Kernel 2: block (56,8) = one d, 8 consecutive h rows (proven-coalesced R4
// shape: w0 = tx*4, warp stores are contiguous 512B runs).
//  Fill: threads tx<14 bilinear-lerp the interleaved 4-channel line for row
//        ty (4x LDG.128), dup entry at iw=14.
//  Main: 4 consecutive w per thread, <=1 knot crossing: G0,G1,G2 once,
//        continuous form u=min(t,1), v=t-u.
//  Diff-softmax: d_i = z_i - z_0;  p_0 = r,  p_i = e_i * r,
//        r = rcp(1 + e1 + e2 + e3).  3x MUFU.EX2 + 1x MUFU.RCP per voxel.
// ---------------------------------------------------------------------------
__global__ __launch_bounds__(448) void upsample_softmax_kernel(float* __restrict__ out) {
    __shared__ __align__(16) float4 gs[8][16];   // 15 used (14 + dup)

    const int tx = threadIdx.x;   // 0..55
    const int ty = threadIdx.y;   // 0..7
    const int d  = blockIdx.y;
    const int h  = blockIdx.x * 8 + ty;

    // ---- fill gs[ty][0..14] (14 threads per row) ----
    if (tx < 14) {
        float pd = (float)d * SCALE;
        int id0 = (int)pd; if (id0 > 12) id0 = 12;
        float wd = pd - (float)id0;
        float ph = (float)h * SCALE;
        int ih0 = (int)ph; if (ih0 > 12) ih0 = 12;
        float wh = ph - (float)ih0;

        const float4* z4 = (const float4*)g_z4;
        int base = (id0 * 14 + ih0) * 14 + tx;
        float4 z00 = z4[base];
        float4 z01 = z4[base + 14];
        float4 z10 = z4[base + 196];
        float4 z11 = z4[base + 210];
        float4 a0, a1, g;
        a0.x = fmaf(wh, z01.x - z00.x, z00.x);
        a0.y = fmaf(wh, z01.y - z00.y, z00.y);
        a0.z = fmaf(wh, z01.z - z00.z, z00.z);
        a0.w = fmaf(wh, z01.w - z00.w, z00.w);
        a1.x = fmaf(wh, z11.x - z10.x, z10.x);
        a1.y = fmaf(wh, z11.y - z10.y, z10.y);
        a1.z = fmaf(wh, z11.z - z10.z, z10.z);
        a1.w = fmaf(wh, z11.w - z10.w, z10.w);
        g.x = fmaf(wd, a1.x - a0.x, a0.x);
        g.y = fmaf(wd, a1.y - a0.y, a0.y);
        g.z = fmaf(wd, a1.z - a0.z, a0.z);
        g.w = fmaf(wd, a1.w - a0.w, a0.w);
        gs[ty][tx] = g;
        if (tx == 13) gs[ty][14] = g;   // dup; its segment weight is always ~0
    }
    __syncthreads();

    // ---- 4 consecutive w per thread ----
    const int w0 = tx * 4;
    float pw0 = (float)w0 * SCALE;        // <= 12.83, no clip needed
    int iw0 = (int)pw0;
    float t0 = pw0 - (float)iw0;

    float4 G0 = gs[ty][iw0];
    float4 G1 = gs[ty][iw0 + 1];
    float4 G2 = gs[ty][iw0 + 2];

    // channel-0 diff basis: d_i(t) = b_i + u*P_i + v*Q_i
    float b1 = G0.y - G0.x, b2 = G0.z - G0.x, b3 = G0.w - G0.x;
    float D0 = G1.x - G0.x;
    float P1 = (G1.y - G0.y) - D0;
    float P2 = (G1.z - G0.z) - D0;
    float P3 = (G1.w - G0.w) - D0;
    float E0 = G2.x - G1.x;
    float Q1 = (G2.y - G1.y) - E0;
    float Q2 = (G2.z - G1.z) - E0;
    float Q3 = (G2.w - G1.w) - E0;

    float r0[4], r1[4], r2[4], r3[4];

#pragma unroll
    for (int k = 0; k < 4; k++) {
        float t = t0 + (float)k * SCALE;   // FADD with immediate
        float u = fminf(t, 1.0f);
        float v = t - u;
        float d1 = fmaf(v, Q1, fmaf(u, P1, b1));
        float d2 = fmaf(v, Q2, fmaf(u, P2, b2));
        float d3 = fmaf(v, Q3, fmaf(u, P3, b3));
        float e1 = exp2f(d1);
        float e2 = exp2f(d2);
        float e3 = exp2f(d3);
        float s = 1.0f + ((e1 + e2) + e3);
        float r;
        asm("rcp.approx.f32 %0, %1;" : "=f"(r) : "f"(s));
        r0[k] = r;
        r1[k] = e1 * r;
        r2[k] = e2 * r;
        r3[k] = e3 * r;
    }

    const int PLANE4 = (224 * 224 * 224) >> 2;
    int idx4 = (((d * 224 + h) * 224 + w0) >> 2);
    float4* o4 = (float4*)out;
    o4[idx4]              = make_float4(r0[0], r0[1], r0[2], r0[3]);
    o4[idx4 + PLANE4]     = make_float4(r1[0], r1[1], r1[2], r1[3]);
    o4[idx4 + 2 * PLANE4] = make_float4(r2[0], r2[1], r2[2], r2[3]);
    o4[idx4 + 3 * PLANE4] = make_float4(r3[0], r3[1], r3[2], r3[3]);
}

extern "C" void kernel_launch(void* const* d_in, const int* in_sizes, int n_in,
                              void* d_out, int out_size) {
    const float* x = (const float*)d_in[0];  // [1,32,14,14,14]
    const float* W = (const float*)d_in[1];  // [4,32]
    const float* b = (const float*)d_in[2];  // [4]
    float* out = (float*)d_out;              // [1,4,224,224,224]

    conv_small_kernel<<<(4 * 2744 + 255) / 256, 256>>>(x, W, b);

    dim3 block(56, 8);
    dim3 grid(28, 224);  // (h-group of 8, d)
    upsample_softmax_kernel<<<grid, block>>>(out);
}

// round 7
// speedup vs baseline: 2.4523x; 1.0093x over previous
#include <cuda_runtime.h>
#include <cuda_bf16.h>
#include <cstdint>

// channel-interleaved logits on the 14^3 grid, pre-scaled by log2(e):
// g_z4[v*4 + c]  (43 KB)
__device__ float g_z4[2744 * 4];

#define LOG2E 1.4426950408889634f
#define SCALE (13.0f / 223.0f)

// ---------------------------------------------------------------------------
// Kernel 1: 1x1x1 conv on the small grid -> interleaved float4 logits.
// ---------------------------------------------------------------------------
__global__ void conv_small_kernel(const float* __restrict__ x,
                                  const float* __restrict__ W,
                                  const float* __restrict__ b) {
    int idx = blockIdx.x * blockDim.x + threadIdx.x;
    if (idx >= 4 * 2744) return;
    int v = idx >> 2;
    int o = idx & 3;
    float acc = b[o];
    const float* wrow = W + o * 32;
#pragma unroll
    for (int c = 0; c < 32; c++) {
        acc = fmaf(wrow[c], x[c * 2744 + v], acc);
    }
    g_z4[idx] = acc * LOG2E;   // coalesced interleaved write
}

// ---------------------------------------------------------------------------
// Kernel 2: block (56,8) covers one d and 16 consecutive h rows; each thread
// produces 4 consecutive w voxels on TWO rows (ty and ty+8).
//  Phase A (224 thr): bilinear (d,h)-lerp the 4-ch line -> gs[row][iw].
//  Phase B (208 thr): per (row, iw0) diff basis b/P/Q (9 floats) -> smem,
//           computed ONCE instead of per-thread (threads sharing iw0 reuse).
//  Main: load 2x3 float4 basis, 4x {u=min(t,1), v=t-u}, per row per voxel:
//           d_i = b_i + u*P_i + v*Q_i, 3x EX2, r = rcp(1+sum), p = e*r.
//  Stores: 8x STG.128, warp-contiguous (w0 = tx*4 preserved).
// ---------------------------------------------------------------------------
__global__ __launch_bounds__(448) void upsample_softmax_kernel(float* __restrict__ out) {
    __shared__ __align__(16) float4 gs[16][16];    // 15 used (14 + dup)
    __shared__ __align__(16) float4 sb[16][40];    // [row][iw0*3 + {B,P,Q}]

    const int tx = threadIdx.x;   // 0..55
    const int ty = threadIdx.y;   // 0..7
    const int d  = blockIdx.y;
    const int h0 = blockIdx.x * 16;
    const int tid = ty * 56 + tx;

    // ---- Phase A: fill gs[row][iw], row 0..15, iw 0..13 ----
    if (tid < 224) {
        int row = tid / 14;
        int iw  = tid - row * 14;
        int h   = h0 + row;

        float pd = (float)d * SCALE;
        int id0 = (int)pd; if (id0 > 12) id0 = 12;
        float wd = pd - (float)id0;
        float ph = (float)h * SCALE;
        int ih0 = (int)ph; if (ih0 > 12) ih0 = 12;
        float wh = ph - (float)ih0;

        const float4* z4 = (const float4*)g_z4;
        int base = (id0 * 14 + ih0) * 14 + iw;
        float4 z00 = z4[base];
        float4 z01 = z4[base + 14];
        float4 z10 = z4[base + 196];
        float4 z11 = z4[base + 210];
        float4 a0, a1, g;
        a0.x = fmaf(wh, z01.x - z00.x, z00.x);
        a0.y = fmaf(wh, z01.y - z00.y, z00.y);
        a0.z = fmaf(wh, z01.z - z00.z, z00.z);
        a0.w = fmaf(wh, z01.w - z00.w, z00.w);
        a1.x = fmaf(wh, z11.x - z10.x, z10.x);
        a1.y = fmaf(wh, z11.y - z10.y, z10.y);
        a1.z = fmaf(wh, z11.z - z10.z, z10.z);
        a1.w = fmaf(wh, z11.w - z10.w, z10.w);
        g.x = fmaf(wd, a1.x - a0.x, a0.x);
        g.y = fmaf(wd, a1.y - a0.y, a0.y);
        g.z = fmaf(wd, a1.z - a0.z, a0.z);
        g.w = fmaf(wd, a1.w - a0.w, a0.w);
        gs[row][iw] = g;
        if (iw == 13) gs[row][14] = g;   // dup; its segment weight is always 0
    }
    __syncthreads();

    // ---- Phase B: diff basis per (row, iw0), iw0 0..12 ----
    if (tid < 208) {
        int row = tid / 13;
        int iw  = tid - row * 13;
        float4 G0 = gs[row][iw];
        float4 G1 = gs[row][iw + 1];
        float4 G2 = gs[row][iw + 2];
        float D0 = G1.x - G0.x;
        float E0 = G2.x - G1.x;
        sb[row][iw * 3 + 0] = make_float4(G0.y - G0.x, G0.z - G0.x, G0.w - G0.x, 0.f);
        sb[row][iw * 3 + 1] = make_float4((G1.y - G0.y) - D0, (G1.z - G0.z) - D0,
                                          (G1.w - G0.w) - D0, 0.f);
        sb[row][iw * 3 + 2] = make_float4((G2.y - G1.y) - E0, (G2.z - G1.z) - E0,
                                          (G2.w - G1.w) - E0, 0.f);
    }
    __syncthreads();

    // ---- Main: 4 consecutive w on rows ty and ty+8 ----
    const int w0 = tx * 4;
    float pw0 = (float)w0 * SCALE;        // <= 12.83
    int iw0 = (int)pw0;
    float t0 = pw0 - (float)iw0;

    float4 Ba = sb[ty][iw0 * 3 + 0];
    float4 Pa = sb[ty][iw0 * 3 + 1];
    float4 Qa = sb[ty][iw0 * 3 + 2];
    float4 Bb = sb[ty + 8][iw0 * 3 + 0];
    float4 Pb = sb[ty + 8][iw0 * 3 + 1];
    float4 Qb = sb[ty + 8][iw0 * 3 + 2];

    float a0[4], a1[4], a2[4], a3[4];
    float c0[4], c1[4], c2[4], c3[4];

#pragma unroll
    for (int k = 0; k < 4; k++) {
        float t = t0 + (float)k * SCALE;
        float u = fminf(t, 1.0f);
        float v = t - u;

        // row a
        {
            float d1 = fmaf(v, Qa.x, fmaf(u, Pa.x, Ba.x));
            float d2 = fmaf(v, Qa.y, fmaf(u, Pa.y, Ba.y));
            float d3 = fmaf(v, Qa.z, fmaf(u, Pa.z, Ba.z));
            float e1 = exp2f(d1);
            float e2 = exp2f(d2);
            float e3 = exp2f(d3);
            float s = 1.0f + ((e1 + e2) + e3);
            float r;
            asm("rcp.approx.f32 %0, %1;" : "=f"(r) : "f"(s));
            a0[k] = r;
            a1[k] = e1 * r;
            a2[k] = e2 * r;
            a3[k] = e3 * r;
        }
        // row b
        {
            float d1 = fmaf(v, Qb.x, fmaf(u, Pb.x, Bb.x));
            float d2 = fmaf(v, Qb.y, fmaf(u, Pb.y, Bb.y));
            float d3 = fmaf(v, Qb.z, fmaf(u, Pb.z, Bb.z));
            float e1 = exp2f(d1);
            float e2 = exp2f(d2);
            float e3 = exp2f(d3);
            float s = 1.0f + ((e1 + e2) + e3);
            float r;
            asm("rcp.approx.f32 %0, %1;" : "=f"(r) : "f"(s));
            c0[k] = r;
            c1[k] = e1 * r;
            c2[k] = e2 * r;
            c3[k] = e3 * r;
        }
    }

    const int PLANE4  = (224 * 224 * 224) >> 2;
    const int ROW8_4  = (8 * 224) >> 2;   // 8 h-rows in float4 units
    int idxa = ((d * 224 + h0 + ty) * 224 + w0) >> 2;
    float4* o4 = (float4*)out;

    o4[idxa]                       = make_float4(a0[0], a0[1], a0[2], a0[3]);
    o4[idxa + PLANE4]              = make_float4(a1[0], a1[1], a1[2], a1[3]);
    o4[idxa + 2 * PLANE4]          = make_float4(a2[0], a2[1], a2[2], a2[3]);
    o4[idxa + 3 * PLANE4]          = make_float4(a3[0], a3[1], a3[2], a3[3]);
    o4[idxa + ROW8_4]              = make_float4(c0[0], c0[1], c0[2], c0[3]);
    o4[idxa + ROW8_4 + PLANE4]     = make_float4(c1[0], c1[1], c1[2], c1[3]);
    o4[idxa + ROW8_4 + 2 * PLANE4] = make_float4(c2[0], c2[1], c2[2], c2[3]);
    o4[idxa + ROW8_4 + 3 * PLANE4] = make_float4(c3[0], c3[1], c3[2], c3[3]);
}

extern "C" void kernel_launch(void* const* d_in, const int* in_sizes, int n_in,
                              void* d_out, int out_size) {
    const float* x = (const float*)d_in[0];  // [1,32,14,14,14]
    const float* W = (const float*)d_in[1];  // [4,32]
    const float* b = (const float*)d_in[2];  // [4]
    float* out = (float*)d_out;              // [1,4,224,224,224]

    conv_small_kernel<<<(4 * 2744 + 255) / 256, 256>>>(x, W, b);

    dim3 block(56, 8);
    dim3 grid(14, 224);  // (h-group of 16, d)
    upsample_softmax_kernel<<<grid, block>>>(out);
}